// round 15
// baseline (speedup 1.0000x reference)
#include <cuda_runtime.h>
#include <cstdint>

// IndRNN fused (sm_103a, baseline-PTX -> warp mma.sync tf32):
// One kernel: grid (4 ntiles x 64 batches). Each CTA computes proj tiles for
// its (b, n0) in t order (4 chunks of 128 timesteps), stages each tile in
// smem, and interleaves the recurrence scan of chunk tc-1 into the MMA
// mainloop of chunk tc. proj never touches gmem: traffic 33.5R + 67W only.

#define M_DIM 32768
#define K_DIM 256
#define U_DIM 512
#define T_DIM 512

// ---------------------------------------------------------------------------
__device__ __forceinline__ uint32_t smem_u32(const void* p) {
    uint32_t a;
    asm("{ .reg .u64 t; cvta.to.shared.u64 t, %1; cvt.u32.u64 %0, t; }" : "=r"(a) : "l"(p));
    return a;
}
__device__ __forceinline__ void cp_async16(uint32_t saddr, const void* gptr) {
    asm volatile("cp.async.cg.shared.global [%0], [%1], 16;" :: "r"(saddr), "l"(gptr));
}
__device__ __forceinline__ void cp_commit() { asm volatile("cp.async.commit_group;"); }
__device__ __forceinline__ void cp_wait0() { asm volatile("cp.async.wait_group 0;"); }

__device__ __forceinline__ uint32_t f2tf32(float f) {
    uint32_t r;
    asm("cvt.rna.tf32.f32 %0, %1;" : "=r"(r) : "f"(f));
    return r;
}
__device__ __forceinline__ void mma16888(float* c, const uint32_t* a, uint32_t b0, uint32_t b1) {
    asm volatile(
        "mma.sync.aligned.m16n8k8.row.col.f32.tf32.tf32.f32 "
        "{%0,%1,%2,%3}, {%4,%5,%6,%7}, {%8,%9}, {%0,%1,%2,%3};"
        : "+f"(c[0]), "+f"(c[1]), "+f"(c[2]), "+f"(c[3])
        : "r"(a[0]), "r"(a[1]), "r"(a[2]), "r"(a[3]), "r"(b0), "r"(b1));
}

// ---------------------------------------------------------------------------
// Smem: double-buffered GEMM stages (R9-proven pitches) + scan tile buffer.
// ---------------------------------------------------------------------------
#define APITCH 144
#define BPITCH 544
#define PART_A (128 * APITCH)
#define PART_B (32 * BPITCH)
#define STAGE_BYTES (PART_A + PART_B)
#define GEMM_SMEM (2 * STAGE_BYTES)            // 71680
#define SBUF_PITCH 132                          // words; scan reads conflict-free
#define SBUF_BYTES (128 * SBUF_PITCH * 4)       // 67584
#define FUSED_SMEM (GEMM_SMEM + SBUF_BYTES)     // 139264

__global__ __launch_bounds__(256) void indrnn_fused(
    const float* __restrict__ X, const float* __restrict__ W,
    const float* __restrict__ bias, const float* __restrict__ h0,
    const float* __restrict__ u, float* __restrict__ out)
{
    extern __shared__ __align__(16) char smem[];
    const uint32_t sbase = smem_u32(smem);
    float* sbuf = (float*)(smem + GEMM_SMEM);

    const int tid = threadIdx.x;
    const int lane = tid & 31, warp = tid >> 5;
    const int wm = (warp & 3) * 32;
    const int wn = (warp >> 2) * 64;
    const int g = lane >> 2, tig = lane & 3;

    const int n0 = blockIdx.x * 128;       // u-tile
    const int b  = blockIdx.y;             // batch

    // Scan state: thread j (<128) owns column u = n0 + j.
    float h = 0.0f, uc = 0.0f;
    if (tid < 128) {
        uc = fminf(fmaxf(u[n0 + tid], 0.0f), 1.0f);
        h = h0[(size_t)b * U_DIM + n0 + tid];
    }

    // Per-CTA bias fragments (uniform across tiles)
    float2 bb[8];
#pragma unroll
    for (int ns = 0; ns < 8; ns++)
        bb[ns] = *(const float2*)(bias + n0 + wn + ns * 8 + 2 * tig);

    // A-load geometry
    int ar[4], ac4[4];
#pragma unroll
    for (int j = 0; j < 4; j++) {
        int q = tid + j * 256;
        ar[j] = q >> 3;
        ac4[j] = q & 7;
    }

    auto ldgA = [&](int row0, int k0, float4* regs) {
#pragma unroll
        for (int j = 0; j < 4; j++)
            regs[j] = *(const float4*)&X[(size_t)(row0 + ar[j]) * K_DIM + k0 + ac4[j] * 4];
    };
    auto stsA = [&](int buf, const float4* regs) {
        char* s0 = smem + buf * STAGE_BYTES;
#pragma unroll
        for (int j = 0; j < 4; j++) {
            uint4 t;
            t.x = f2tf32(regs[j].x);
            t.y = f2tf32(regs[j].y);
            t.z = f2tf32(regs[j].z);
            t.w = f2tf32(regs[j].w);
            *(uint4*)(s0 + ar[j] * APITCH + ac4[j] * 16) = t;
        }
    };
    auto cpB = [&](int buf, int k0) {
        const uint32_t s0 = sbase + buf * STAGE_BYTES + PART_A;
#pragma unroll
        for (int j = 0; j < 4; j++) {
            int c = tid + j * 256;
            int r = c >> 5, unit = c & 31;
            cp_async16(s0 + r * BPITCH + unit * 16,
                       W + (size_t)(k0 + r) * U_DIM + n0 + unit * 4);
        }
    };

    const int NKT = K_DIM / 32;  // 8
    float4 regs[4];

    // Preload first tile's first A chunk
    ldgA(b * T_DIM, 0, regs);

    for (int tc = 0; tc < 4; tc++) {
        const int m0 = b * T_DIM + tc * 128;

        float acc[2][8][4];
#pragma unroll
        for (int ms = 0; ms < 2; ms++)
#pragma unroll
            for (int ns = 0; ns < 8; ns++)
#pragma unroll
                for (int i = 0; i < 4; i++) acc[ms][ns][i] = 0.0f;

        // Prologue (regs already hold chunk 0 of this tile)
        cpB(0, 0);
        cp_commit();
        stsA(0, regs);
        ldgA(m0, 32, regs);
        cp_wait0();
        __syncthreads();

        for (int kt = 0; kt < NKT; kt++) {
            const int buf = kt & 1;

            if (kt + 1 < NKT) {
                stsA(buf ^ 1, regs);
                cpB(buf ^ 1, (kt + 1) * 32);
                cp_commit();
            }
            if (kt + 2 < NKT) {
                ldgA(m0, (kt + 2) * 32, regs);
            } else if (kt + 2 == NKT && tc < 3) {
                ldgA(m0 + 128, 0, regs);   // prefetch next tile chunk 0
            }

            const char* sA = smem + buf * STAGE_BYTES;
            const char* sB = sA + PART_A;

#pragma unroll
            for (int ks = 0; ks < 4; ks++) {
                const int cb = ks * 32 + tig * 4;
                uint32_t a[2][4];
#pragma unroll
                for (int ms = 0; ms < 2; ms++) {
                    const int r = wm + ms * 16 + g;
                    a[ms][0] = *(const uint32_t*)(sA + r * APITCH + cb);
                    a[ms][1] = *(const uint32_t*)(sA + (r + 8) * APITCH + cb);
                    a[ms][2] = *(const uint32_t*)(sA + r * APITCH + cb + 16);
                    a[ms][3] = *(const uint32_t*)(sA + (r + 8) * APITCH + cb + 16);
                }
                const char* bn = sB + (ks * 8 + tig) * BPITCH + (wn + g) * 4;
#pragma unroll
                for (int ns = 0; ns < 8; ns++) {
                    uint32_t b0 = f2tf32(*(const float*)(bn + ns * 32));
                    uint32_t b1 = f2tf32(*(const float*)(bn + 4 * BPITCH + ns * 32));
#pragma unroll
                    for (int ms = 0; ms < 2; ms++)
                        mma16888(acc[ms][ns], a[ms], b0, b1);
                }
            }

            // Interleaved scan: 16 t-steps of tile tc-1 under the MMA shadow.
            if (tc > 0 && tid < 128) {
                float* qrow = out + ((size_t)(m0 - 128) + kt * 16) * U_DIM + n0 + tid;
                const float* srow = sbuf + (kt * 16) * SBUF_PITCH + tid;
#pragma unroll
                for (int i = 0; i < 16; i++) {
                    float v = srow[i * SBUF_PITCH];
                    h = fmaxf(fmaf(h, uc, v), 0.0f);
                    qrow[(size_t)i * U_DIM] = h;
                }
            }

            if (kt + 1 < NKT) cp_wait0();
            __syncthreads();
        }

        // Epilogue: acc + bias -> scan smem buffer (proj tile, fp32)
#pragma unroll
        for (int ns = 0; ns < 8; ns++) {
            const int nn = wn + ns * 8 + 2 * tig;
#pragma unroll
            for (int ms = 0; ms < 2; ms++) {
                const int m = wm + ms * 16 + g;
                float2 o0, o1;
                o0.x = acc[ms][ns][0] + bb[ns].x;
                o0.y = acc[ms][ns][1] + bb[ns].y;
                o1.x = acc[ms][ns][2] + bb[ns].x;
                o1.y = acc[ms][ns][3] + bb[ns].y;
                *(float2*)(sbuf + m * SBUF_PITCH + nn) = o0;
                *(float2*)(sbuf + (m + 8) * SBUF_PITCH + nn) = o1;
            }
        }
        __syncthreads();
    }

    // Final standalone scan: tile tc=3 (t = 384..511)
    if (tid < 128) {
        float* qrow = out + ((size_t)b * T_DIM + 384) * U_DIM + n0 + tid;
        const float* srow = sbuf + tid;
#pragma unroll 16
        for (int t = 0; t < 128; t++) {
            float v = srow[t * SBUF_PITCH];
            h = fmaxf(fmaf(h, uc, v), 0.0f);
            qrow[(size_t)t * U_DIM] = h;
        }
    }
}

// ---------------------------------------------------------------------------
// Fallback path (any shape): naive GEMM into out, then in-place scalar scan.
// ---------------------------------------------------------------------------
__global__ void indrnn_gemm_naive(
    const float* __restrict__ A, const float* __restrict__ Bw,
    const float* __restrict__ bias, float* __restrict__ Cc,
    int M, int N, int K)
{
    int idx = blockIdx.x * blockDim.x + threadIdx.x;
    if (idx >= M * N) return;
    int m = idx / N, n = idx % N;
    float s = bias[n];
    for (int k = 0; k < K; k++) s = fmaf(A[(size_t)m * K + k], Bw[(size_t)k * N + n], s);
    Cc[idx] = s;
}

__global__ __launch_bounds__(128) void indrnn_scan1(
    float* __restrict__ out, const float* __restrict__ h0,
    const float* __restrict__ u, int B, int T, int U)
{
    int idx = blockIdx.x * blockDim.x + threadIdx.x;
    if (idx >= B * U) return;
    int b = idx / U;
    int j = idx - b * U;
    float uc = fminf(fmaxf(u[j], 0.0f), 1.0f);
    float h = h0[idx];
    float* p = out + (size_t)b * T * U + j;
    for (int t = 0; t < T; t++) {
        float v = __ldcg(p);
        h = fmaxf(fmaf(h, uc, v), 0.0f);
        *p = h;
        p += (size_t)U;
    }
}

// ---------------------------------------------------------------------------
extern "C" void kernel_launch(void* const* d_in, const int* in_sizes, int n_in,
                              void* d_out, int out_size)
{
    const float* x  = (const float*)d_in[0];
    const float* h0 = (const float*)d_in[1];
    const float* W  = (const float*)d_in[2];
    const float* u  = (const float*)d_in[3];
    const float* bb = (const float*)d_in[4];
    float* out = (float*)d_out;

    const int U = in_sizes[3];
    const int B = in_sizes[1] / U;
    const int D = in_sizes[2] / U;
    const int T = in_sizes[0] / (B * D);

    const int M = B * T;
    const int N = U;
    const int K = D;

    if (M == M_DIM && N == U_DIM && K == K_DIM && T == T_DIM) {
        cudaFuncSetAttribute(indrnn_fused,
                             cudaFuncAttributeMaxDynamicSharedMemorySize, FUSED_SMEM);
        indrnn_fused<<<dim3(U_DIM / 128, B), 256, FUSED_SMEM>>>(x, W, bb, h0, u, out);
    } else {
        int total = M * N;
        indrnn_gemm_naive<<<(total + 255) / 256, 256>>>(x, W, bb, out, M, N, K);
        int chains = B * U;
        indrnn_scan1<<<(chains + 127) / 128, 128>>>(out, h0, u, B, T, U);
    }
}